// round 17
// baseline (speedup 1.0000x reference)
#include <cuda_runtime.h>
#include <cuda_fp16.h>
#include <cstdint>

#define B_  4
#define S_  2048
#define D_  1024
#define H_  16
#define DK_ 64
#define M_  (B_*S_)    // 8192
#define N_  (H_*DK_)   // 1024
#define KD_ D_         // 1024

// ---------------- device scratch (allocation-free rule: device globals) ----
__device__ __half g_xhi[3*M_*KD_];      // per z: Q,K,V inputs fp16
__device__ __half g_wThi[3*N_*KD_];     // per z: W transposed [n][k]
__device__ __half g_qh[B_*H_*S_*DK_];   // [bh][s][64]
__device__ __half g_kh[B_*H_*S_*DK_];
__device__ __half g_vth[B_*H_*DK_*S_];  // V^T: [bh][d][s]

// ---------------- helpers ---------------------------------------------------
__device__ __forceinline__ uint32_t smem_u32(const void* p) {
    uint32_t a;
    asm("{ .reg .u64 t; cvta.to.shared.u64 t, %1; cvt.u32.u64 %0, t; }"
        : "=r"(a) : "l"(p));
    return a;
}
__device__ __forceinline__ void cp16(void* dst, const void* src) {
    asm volatile("cp.async.cg.shared.global [%0], [%1], 16;"
                 :: "r"(smem_u32(dst)), "l"(src));
}
#define CP_COMMIT() asm volatile("cp.async.commit_group;" ::: "memory")
#define CP_WAIT1()  asm volatile("cp.async.wait_group 1;" ::: "memory")
#define CP_WAIT0()  asm volatile("cp.async.wait_group 0;" ::: "memory")

__device__ __forceinline__ void mma_f16(float* d,
                                        uint32_t a0, uint32_t a1, uint32_t a2, uint32_t a3,
                                        uint32_t b0, uint32_t b1)
{
    asm volatile(
        "mma.sync.aligned.m16n8k16.row.col.f32.f16.f16.f32 "
        "{%0,%1,%2,%3}, {%4,%5,%6,%7}, {%8,%9}, {%0,%1,%2,%3};"
        : "+f"(d[0]), "+f"(d[1]), "+f"(d[2]), "+f"(d[3])
        : "r"(a0), "r"(a1), "r"(a2), "r"(a3), "r"(b0), "r"(b1));
}
__device__ __forceinline__ void ldsm4(uint32_t* r, uint32_t addr) {
    asm volatile("ldmatrix.sync.aligned.m8n8.x4.shared.b16 {%0,%1,%2,%3}, [%4];"
                 : "=r"(r[0]), "=r"(r[1]), "=r"(r[2]), "=r"(r[3]) : "r"(addr));
}
__device__ __forceinline__ uint32_t pack_f16x2(float lo, float hi) {
    uint32_t r;
    asm("cvt.rn.f16x2.f32 %0, %1, %2;" : "=r"(r) : "f"(hi), "f"(lo));
    return r;
}

// ---------------- fused prep: X fp32->fp16 convert + W transpose-convert ----
// grid (9216, 1, 3): bx < 8192 -> X convert (z selects Q/K/V);
//                    bx >= 8192 -> W 32x32 transpose tile (z selects Wq/Wk/Wv)
#define NX_BLOCKS 8192

__global__ __launch_bounds__(256) void prep_kernel(
    const float4* __restrict__ x0, const float4* __restrict__ x1,
    const float4* __restrict__ x2,
    const float* __restrict__ w0, const float* __restrict__ w1,
    const float* __restrict__ w2,
    uint2* __restrict__ xhi, __half* __restrict__ wT)
{
    __shared__ float t[32][33];
    const int tid = threadIdx.x;
    const int z   = blockIdx.z;
    if (blockIdx.x < NX_BLOCKS) {
        const int n4 = (M_ * KD_) / 4;           // 2,097,152 = 8192*256
        int i = blockIdx.x * 256 + tid;
        const float4* x = (z == 0) ? x0 : (z == 1) ? x1 : x2;
        float4 v = x[i];
        uint2 h;
        h.x = pack_f16x2(v.x, v.y);
        h.y = pack_f16x2(v.z, v.w);
        xhi[(size_t)z * n4 + i] = h;
    } else {
        int wt = blockIdx.x - NX_BLOCKS;         // 0..1023
        int n0 = (wt & 31) * 32;
        int k0 = (wt >> 5) * 32;
        int tx = tid & 31, ty = tid >> 5;        // 32 x 8
        const float* w = (z == 0) ? w0 : (z == 1) ? w1 : w2;
        const size_t zo = (size_t)z * N_ * KD_;
        #pragma unroll
        for (int i = 0; i < 4; i++)
            t[ty + i * 8][tx] = w[(size_t)(k0 + ty + i * 8) * N_ + n0 + tx];
        __syncthreads();
        #pragma unroll
        for (int i = 0; i < 4; i++) {
            int n = n0 + ty + i * 8;
            int k = k0 + tx;
            wT[zo + (size_t)n * KD_ + k] = __float2half(t[tx][ty + i * 8]);
        }
    }
}

// ---------------- batched single-term fp16 projection GEMM ------------------
// BM=64, BN=128, BK=32; 256 threads; warp tile 32x32; 3-stage ring, 1 barrier.
#define PAD      40
#define MATA_B   (64 * PAD * 2)     // 5120
#define MATB_B   (128 * PAD * 2)    // 10240
#define PSTG     (MATA_B + MATB_B)  // 15360
#define NKCH     (KD_ / 32)

__global__ __launch_bounds__(256, 3) void proj_all_kernel(
    const float* __restrict__ bq, const float* __restrict__ bk,
    const float* __restrict__ bv)
{
    extern __shared__ char psm[];

    const int tid  = threadIdx.x;
    const int wid  = tid >> 5;
    const int lane = tid & 31;
    const int wm   = wid >> 2;          // 0..1 (32 m-rows each)
    const int wn   = wid & 3;           // 0..3 (32 n-cols each)
    const int bm   = blockIdx.y * 64;
    const int bn   = blockIdx.x * 128;
    const int z    = blockIdx.z;

    const __half* xhi  = g_xhi  + (size_t)z * M_ * KD_;
    const __half* whiT = g_wThi + (size_t)z * N_ * KD_;
    const float* bias = (z == 0) ? bq : (z == 1) ? bk : bv;
    const float scale = (z == 0) ? 0.125f : 1.0f;

    float acc[2][4][4];
    #pragma unroll
    for (int i = 0; i < 2; i++)
        #pragma unroll
        for (int j = 0; j < 4; j++)
            #pragma unroll
            for (int r = 0; r < 4; r++) acc[i][j][r] = 0.f;

    // A: 64x4 units=256, B: 128x4=512 -> 768 units over 256 threads
    auto load_stage = [&](int c, int s) {
        const int k0 = c * 32;
        char* st = psm + s * PSTG;
        #pragma unroll
        for (int t = 0; t < 3; t++) {
            int idx = tid + t * 256;
            if (idx < 256) {
                int rr = idx >> 2, u = idx & 3;
                cp16(st + rr * (PAD * 2) + u * 16,
                     xhi + (size_t)(bm + rr) * KD_ + k0 + u * 8);
            } else {
                int i2 = idx - 256;
                int rr = i2 >> 2, u = i2 & 3;
                cp16(st + MATA_B + rr * (PAD * 2) + u * 16,
                     whiT + (size_t)(bn + rr) * KD_ + k0 + u * 8);
            }
        }
        CP_COMMIT();
    };

    const int fr   = lane >> 2;
    const int fc   = (lane & 3) * 2;
    const int lrow = lane & 7;
    const int lm   = lane >> 3;
    const uint32_t psm_u = smem_u32(psm);

    auto compute = [&](int s) {
        const uint32_t aHi = psm_u + s * PSTG;
        const uint32_t bHi = aHi + MATA_B;
        #pragma unroll
        for (int ks = 0; ks < 2; ks++) {
            const int kc = ks * 16;
            const uint32_t aoff = (uint32_t)(((lm & 1) * 8 + lrow) * (PAD * 2)
                                             + (kc + (lm >> 1) * 8) * 2);
            const uint32_t boff = (uint32_t)(((lm >> 1) * 8 + lrow) * (PAD * 2)
                                             + (kc + (lm & 1) * 8) * 2);
            uint32_t af[2][4], bh[8];
            #pragma unroll
            for (int i = 0; i < 2; i++) {
                uint32_t ra = (uint32_t)((wm * 32 + i * 16) * (PAD * 2));
                ldsm4(af[i], aHi + ra + aoff);
            }
            #pragma unroll
            for (int jb = 0; jb < 2; jb++) {
                uint32_t rb = (uint32_t)((wn * 32 + jb * 16) * (PAD * 2));
                ldsm4(&bh[jb * 4], bHi + rb + boff);
            }
            #pragma unroll
            for (int i = 0; i < 2; i++)
                #pragma unroll
                for (int j = 0; j < 4; j++)
                    mma_f16(acc[i][j], af[i][0], af[i][1], af[i][2], af[i][3],
                            bh[j * 2], bh[j * 2 + 1]);
        }
    };

    load_stage(0, 0);
    load_stage(1, 1);
    for (int c = 0; c < NKCH; c++) {
        if (c + 1 < NKCH) { CP_WAIT1(); } else { CP_WAIT0(); }
        __syncthreads();
        compute(c % 3);
        if (c + 2 < NKCH) load_stage(c + 2, (c + 2) % 3);
    }

    // epilogue: bias+scale, round to fp16, write (V transposed when z==2)
    #pragma unroll
    for (int i = 0; i < 2; i++) {
        #pragma unroll
        for (int rr = 0; rr < 2; rr++) {
            int m = bm + wm * 32 + i * 16 + fr + rr * 8;
            int b = m >> 11;
            int sdx = m & (S_ - 1);
            #pragma unroll
            for (int j = 0; j < 4; j++) {
                int n0 = bn + wn * 32 + j * 8 + fc;
                int h  = n0 >> 6;
                int d  = n0 & 63;
                float x0 = (acc[i][j][rr * 2 + 0] + bias[n0 + 0]) * scale;
                float x1 = (acc[i][j][rr * 2 + 1] + bias[n0 + 1]) * scale;
                __half h0 = __float2half(x0);
                __half h1 = __float2half(x1);
                if (z == 0) {
                    size_t o = (((size_t)(b * H_ + h) * S_) + sdx) * DK_ + d;
                    __half2 ph; ph.x = h0; ph.y = h1;
                    *(__half2*)&g_qh[o] = ph;
                } else if (z == 1) {
                    size_t o = (((size_t)(b * H_ + h) * S_) + sdx) * DK_ + d;
                    __half2 ph; ph.x = h0; ph.y = h1;
                    *(__half2*)&g_kh[o] = ph;
                } else {
                    size_t o = ((size_t)(b * H_ + h) * DK_ + d) * S_ + sdx;
                    g_vth[o] = h0; g_vth[o + S_] = h1;
                }
            }
        }
    }
}

// ---------------- tensor-core attention ------------------------------------
// BR=64, 4 warps x 16 q-rows (128 threads), 3-stage ring, 1 barrier/chunk.
#define BR   64
#define ATH  128
#define KC   64
#define NCHA (S_ / KC)     // 32
#define QSTR 144           // bytes/row (72 halves)
#define KMAT (64 * QSTR)   // 9216
#define STG  (2 * KMAT + 256)      // 18688 (kh + vh + mask)
#define OFFK (BR * QSTR)           // 9216 (after qh)

__global__ __launch_bounds__(ATH, 3) void attn_mma_kernel(
    const float* __restrict__ maskg, float* __restrict__ out)
{
    extern __shared__ char smc[];

    const int tid  = threadIdx.x;
    const int wid  = tid >> 5;           // 0..3
    const int lane = tid & 31;
    const int fr   = lane >> 2;
    const int fc   = (lane & 3) * 2;
    const int lrow = lane & 7;
    const int lm   = lane >> 3;
    const int bh   = blockIdx.y;
    const int b    = bh >> 4;
    const int h    = bh & 15;
    const int bm   = blockIdx.x * BR;
    const int wq0  = wid * 16;

    const __half* qh_g = g_qh + ((size_t)bh * S_ + bm) * DK_;

    // Q load (joins chunk 0's commit group): 512 16B units over 128 threads
    #pragma unroll
    for (int t = 0; t < 4; t++) {
        int idx = tid + t * ATH;
        int r = idx >> 3, u = idx & 7;
        cp16(smc + r * QSTR + u * 16, qh_g + r * DK_ + u * 8);
    }

    auto load_chunk = [&](int c, int s) {
        const int k0 = c * KC;
        char* st = smc + OFFK + s * STG;
        #pragma unroll
        for (int t = 0; t < 4; t++) {
            int idx = tid + t * ATH;      // 0..511 : 64 rows x 8 units
            int r = idx >> 3, u = idx & 7;
            cp16(st + r * QSTR + u * 16,
                 g_kh + ((size_t)bh * S_ + k0 + r) * DK_ + u * 8);
            cp16(st + KMAT + r * QSTR + u * 16,
                 g_vth + ((size_t)bh * DK_ + r) * S_ + k0 + u * 8);
        }
        if (tid < 16) cp16(st + 2 * KMAT + tid * 16, maskg + (size_t)b * S_ + k0 + tid * 4);
        CP_COMMIT();
    };

    load_chunk(0, 0);
    load_chunk(1, 1);

    uint32_t qf[4][4];
    float accO[8][4];
    #pragma unroll
    for (int n = 0; n < 8; n++)
        #pragma unroll
        for (int r = 0; r < 4; r++) accO[n][r] = 0.f;
    float den0 = 0.f, den1 = 0.f;

    const uint32_t smc_u = smem_u32(smc);
    const uint32_t lboff = (uint32_t)(((lm >> 1) * 8 + lrow) * QSTR + (lm & 1) * 16);

    for (int c = 0; c < NCHA; c++) {
        const int s = c % 3;
        if (c + 1 < NCHA) { CP_WAIT1(); } else { CP_WAIT0(); }
        __syncthreads();

        if (c == 0) {
            const char* qhB = smc;
            int r0 = wq0 + fr;
            #pragma unroll
            for (int kt = 0; kt < 4; kt++) {
                int cb = (kt * 16 + fc) * 2;
                qf[kt][0] = *(const uint32_t*)(qhB + r0 * QSTR + cb);
                qf[kt][1] = *(const uint32_t*)(qhB + (r0 + 8) * QSTR + cb);
                qf[kt][2] = *(const uint32_t*)(qhB + r0 * QSTR + cb + 16);
                qf[kt][3] = *(const uint32_t*)(qhB + (r0 + 8) * QSTR + cb + 16);
            }
        }

        const uint32_t khu = smc_u + OFFK + (uint32_t)(s * STG);
        const uint32_t vhu = khu + KMAT;
        const float* mk = (const float*)(smc + OFFK + s * STG + 2 * KMAT);

        // ---- scores (fp16, 1 term)
        float accs[8][4];
        #pragma unroll
        for (int n = 0; n < 8; n++)
            #pragma unroll
            for (int r = 0; r < 4; r++) accs[n][r] = 0.f;

        #pragma unroll
        for (int kt = 0; kt < 4; kt++) {
            #pragma unroll
            for (int np = 0; np < 4; np++) {
                uint32_t off = (uint32_t)(np * 16 * QSTR + kt * 32) + lboff;
                uint32_t bh4[4];
                ldsm4(bh4, khu + off);
                mma_f16(accs[2*np],   qf[kt][0], qf[kt][1], qf[kt][2], qf[kt][3], bh4[0], bh4[1]);
                mma_f16(accs[2*np+1], qf[kt][0], qf[kt][1], qf[kt][2], qf[kt][3], bh4[2], bh4[3]);
            }
        }

        // ---- P = exp(s) * mask; fp16 pack; denom (fp32, pre-rounding)
        uint32_t phf[4][4];
        #pragma unroll
        for (int nt = 0; nt < 8; nt++) {
            float m0 = mk[nt * 8 + fc];
            float m1 = mk[nt * 8 + fc + 1];
            #pragma unroll
            for (int rr = 0; rr < 2; rr++) {
                float p0 = __expf(accs[nt][rr * 2 + 0]) * m0;
                float p1 = __expf(accs[nt][rr * 2 + 1]) * m1;
                if (rr == 0) den0 += p0 + p1; else den1 += p0 + p1;
                phf[nt >> 1][(nt & 1) * 2 + rr] = pack_f16x2(p0, p1);
            }
        }

        // ---- O += P @ V (fp16, 1 term)
        #pragma unroll
        for (int kt = 0; kt < 4; kt++) {
            #pragma unroll
            for (int np = 0; np < 4; np++) {
                uint32_t off = (uint32_t)(np * 16 * QSTR + kt * 32) + lboff;
                uint32_t vh4[4];
                ldsm4(vh4, vhu + off);
                mma_f16(accO[2*np],   phf[kt][0], phf[kt][1], phf[kt][2], phf[kt][3], vh4[0], vh4[1]);
                mma_f16(accO[2*np+1], phf[kt][0], phf[kt][1], phf[kt][2], phf[kt][3], vh4[2], vh4[3]);
            }
        }

        if (c + 2 < NCHA) load_chunk(c + 2, (c + 2) % 3);
    }

    den0 += __shfl_xor_sync(0xffffffffu, den0, 1);
    den0 += __shfl_xor_sync(0xffffffffu, den0, 2);
    den1 += __shfl_xor_sync(0xffffffffu, den1, 1);
    den1 += __shfl_xor_sync(0xffffffffu, den1, 2);
    float inv0 = 1.f / (den0 + 1e-8f);
    float inv1 = 1.f / (den1 + 1e-8f);

    int q = bm + wq0 + fr;
    #pragma unroll
    for (int nt = 0; nt < 8; nt++) {
        int col = h * DK_ + nt * 8 + fc;
        float2 o0; o0.x = accO[nt][0] * inv0; o0.y = accO[nt][1] * inv0;
        float2 o1; o1.x = accO[nt][2] * inv1; o1.y = accO[nt][3] * inv1;
        *(float2*)&out[((size_t)(b * S_ + q)) * N_ + col] = o0;
        *(float2*)&out[((size_t)(b * S_ + q + 8)) * N_ + col] = o1;
    }
}

// ---------------------------------------------------------------------------
extern "C" void kernel_launch(void* const* d_in, const int* in_sizes, int n_in,
                              void* d_out, int out_size)
{
    const float* Q    = (const float*)d_in[0];
    const float* Kin  = (const float*)d_in[1];
    const float* Vin  = (const float*)d_in[2];
    const float* mask = (const float*)d_in[3];
    const float* Wq   = (const float*)d_in[4];
    const float* bq   = (const float*)d_in[5];
    const float* Wk   = (const float*)d_in[6];
    const float* bk   = (const float*)d_in[7];
    const float* Wv   = (const float*)d_in[8];
    const float* bv   = (const float*)d_in[9];
    float* out = (float*)d_out;

    __half *xhi, *whiT;
    cudaGetSymbolAddress((void**)&xhi,  g_xhi);
    cudaGetSymbolAddress((void**)&whiT, g_wThi);

    prep_kernel<<<dim3(NX_BLOCKS + 1024, 1, 3), 256>>>(
        (const float4*)Q, (const float4*)Kin, (const float4*)Vin,
        Wq, Wk, Wv, (uint2*)xhi, whiT);

    const int psmem = 3 * PSTG;   // 46080
    cudaFuncSetAttribute(proj_all_kernel,
                         cudaFuncAttributeMaxDynamicSharedMemorySize, psmem);
    proj_all_kernel<<<dim3(N_ / 128, M_ / 64, 3), 256, psmem>>>(bq, bk, bv);

    const int asmem = OFFK + 3 * STG;   // 9216 + 56064 = 65280
    cudaFuncSetAttribute(attn_mma_kernel,
                         cudaFuncAttributeMaxDynamicSharedMemorySize, asmem);
    attn_mma_kernel<<<dim3(S_ / BR, B_ * H_), ATH, asmem>>>(mask, out);
}